// round 1
// baseline (speedup 1.0000x reference)
#include <cuda_runtime.h>

// ISTFT: B=16, C=2, F=257, T=2048, n_fft=512, hop=128, center=True, hann window input.
// Stage 1: per-frame inverse real FFT (via 256-pt complex Stockham IFFT) + window -> scratch
// Stage 2: overlap-add gather + window-envelope normalize -> output

#define NFFT     512
#define NH       257          // onesided bins
#define MHALF    256          // complex IFFT length
#define HOP      128
#define TFRAMES  2048
#define NBC      32           // B*C
#define NFRAMES  (NBC * TFRAMES)       // 65536
#define OUT_PER_BC 262016              // (T-1)*hop
#define THREADS  256
#define FPB      8            // frames per block

// 256 MiB deterministic scratch (allowed: static __device__ array)
static __device__ float g_frames[(size_t)NFRAMES * NFFT];

__global__ __launch_bounds__(THREADS)
void istft_frames_kernel(const float2* __restrict__ X, const float* __restrict__ win)
{
    // Two ping-pong buffers (257 wide: holds the 257 input bins; odd stride also
    // de-patterns shared banks), twiddle tables, scaled window.
    __shared__ float2 A [FPB][NH];
    __shared__ float2 Bb[FPB][NH];
    __shared__ float2 Wt[128];     // cis(+2*pi*j/256)
    __shared__ float2 T5[256];     // cis(+2*pi*k/512)
    __shared__ float  wsh[NFFT];   // window / 256

    const int tid = threadIdx.x;

    for (int j = tid; j < 128; j += THREADS) {
        float s, c; sincospif(j * (1.0f / 128.0f), &s, &c);  // 2*pi*j/256
        Wt[j] = make_float2(c, s);
    }
    for (int k = tid; k < 256; k += THREADS) {
        float s, c; sincospif(k * (1.0f / 256.0f), &s, &c);  // 2*pi*k/512
        T5[k] = make_float2(c, s);
    }
    for (int n = tid; n < NFFT; n += THREADS)
        wsh[n] = win[n] * (1.0f / 256.0f);                   // fold IFFT 1/M scale

    const int f0 = blockIdx.x * FPB;          // first frame of this block
    const int bc = f0 >> 11;                  // / 2048
    const int t0 = f0 & (TFRAMES - 1);

    // Load 8 frames x 257 bins. For fixed k, the 8 frames are consecutive in t ->
    // 64B-contiguous float2 runs, well coalesced.
    for (int idx = tid; idx < NH * FPB; idx += THREADS) {
        const int k  = idx >> 3;
        const int fr = idx & 7;
        A[fr][k] = X[(size_t)(bc * NH + k) * TFRAMES + t0 + fr];
    }
    __syncthreads();

    // Pack one-sided spectrum into 256-pt complex spectrum Z (into Bb):
    //   Ze = (X[k] + conj(X[256-k]))/2
    //   Zo = cis(+2*pi*k/512) * (i/2) * (X[k] - conj(X[256-k]))
    //   Z  = Ze + Zo
    // DC / Nyquist imaginary parts are ignored (C2R semantics).
    for (int idx = tid; idx < FPB * MHALF; idx += THREADS) {
        const int fr = idx >> 8;
        const int k  = idx & 255;
        float2 a = A[fr][k];
        float2 t = A[fr][MHALF - k];
        float br = t.x, bi = -t.y;            // conj
        if (k == 0) { a.y = 0.0f; bi = 0.0f; }
        const float zer = 0.5f * (a.x + br);
        const float zei = 0.5f * (a.y + bi);
        const float dr  = a.x - br;
        const float di  = a.y - bi;
        const float u   = -0.5f * di;         // (i/2)*d
        const float v   =  0.5f * dr;
        const float2 w  = T5[k];
        Bb[fr][k] = make_float2(zer + w.x * u - w.y * v,
                                zei + w.x * v + w.y * u);
    }
    __syncthreads();

    // 8 Stockham radix-2 DIF stages, inverse (e^{+i}), unnormalized.
    // Stage st: n = 256>>st, m = n/2 = 128>>st, s = 1<<st.
    //   y[q + s*2p]     = a + b
    //   y[q + s*(2p+1)] = (a - b) * cis(2*pi*p/n)
    // with a = x[q+s*p], b = x[q+s*p+128] (s*m == 128 every stage).
    {
        float2 (*src)[NH] = Bb;
        float2 (*dst)[NH] = A;
        #pragma unroll
        for (int st = 0; st < 8; st++) {
            for (int bf = tid; bf < FPB * 128; bf += THREADS) {
                const int fr = bf >> 7;
                const int i  = bf & 127;
                const int p  = i >> st;
                const int q  = i & ((1 << st) - 1);
                const int ia = q + (p << st);
                const float2 a = src[fr][ia];
                const float2 b = src[fr][ia + 128];
                const int io = q + (p << (st + 1));
                dst[fr][io] = make_float2(a.x + b.x, a.y + b.y);
                const float2 w = Wt[p << st];
                const float dr = a.x - b.x;
                const float di = a.y - b.y;
                dst[fr][io + (1 << st)] = make_float2(w.x * dr - w.y * di,
                                                      w.x * di + w.y * dr);
            }
            __syncthreads();
            float2 (*tmp)[NH] = src; src = dst; dst = tmp;
        }
        // 8 stages starting src=Bb: result ends in Bb.
    }

    // Unpack interleaved real output y[2m]=Re z[m], y[2m+1]=Im z[m];
    // apply window * 1/256; store coalesced to scratch.
    for (int idx = tid; idx < FPB * NFFT; idx += THREADS) {
        const int fr = idx >> 9;
        const int nn = idx & (NFFT - 1);
        const float2 z = Bb[fr][nn >> 1];
        const float v = (nn & 1) ? z.y : z.x;
        g_frames[(size_t)(f0 + fr) * NFFT + nn] = v * wsh[nn];
    }
}

__global__ __launch_bounds__(THREADS)
void istft_ola_kernel(const float* __restrict__ win, float* __restrict__ out, int total)
{
    __shared__ float wsh[NFFT];
    for (int n = threadIdx.x; n < NFFT; n += THREADS) wsh[n] = win[n];
    __syncthreads();

    const int j = blockIdx.x * THREADS + threadIdx.x;
    if (j >= total) return;

    const int bc = j / OUT_PER_BC;
    const int jj = j - bc * OUT_PER_BC;
    const int m  = jj + (NFFT / 2);           // center=True trim

    int thi = m >> 7;           if (thi > TFRAMES - 1) thi = TFRAMES - 1;
    int tlo = (m - 384) >> 7;   if (tlo < 0) tlo = 0;   // ceil((m-511)/128)

    float acc = 0.0f, env = 0.0f;
    #pragma unroll 4
    for (int t = tlo; t <= thi; t++) {
        const int n = m - (t << 7);
        acc += g_frames[(size_t)(bc * TFRAMES + t) * NFFT + n];
        const float w = wsh[n];
        env += w * w;
    }
    out[j] = acc / env;
}

extern "C" void kernel_launch(void* const* d_in, const int* in_sizes, int n_in,
                              void* d_out, int out_size)
{
    const float2* X   = (const float2*)d_in[0];   // (16,2,257,2048,2) f32 -> float2
    const float*  win = (const float*)d_in[1];    // (512,) f32
    float* out = (float*)d_out;                   // (16,2,262016) f32

    istft_frames_kernel<<<NFRAMES / FPB, THREADS>>>(X, win);

    const int total = NBC * OUT_PER_BC;           // 8384512
    istft_ola_kernel<<<(total + THREADS - 1) / THREADS, THREADS>>>(win, out, total);
}

// round 2
// speedup vs baseline: 1.0616x; 1.0616x over previous
#include <cuda_runtime.h>

// Fused ISTFT: B=16, C=2, F=257, T=2048, n_fft=512, hop=128, center=True.
// One kernel: block = 16 consecutive frames of one (b,c) stream ->
//   stage input -> pack to 256-pt complex spectrum -> 4 paired-radix-2 (radix-4)
//   Stockham stages in SMEM -> unpack+window -> overlap-add 1664 output samples.
// Blocks advance 13 frames (4x-overlap window needs 3 frames of halo).

#define NFFT     512
#define NH       257
#define HOP      128
#define TFRAMES  2048
#define NBC      32
#define OUT_PER_BC 262016            // (T-1)*hop
#define THREADS  256
#define FPB      16                  // frames per block
#define FADV     13                  // frame advance per chunk
#define CHUNK    1664                // FADV*HOP samples per chunk
#define NCHUNK   158                 // ceil(262016/1664)

// XOR swizzle to de-pattern strided Stockham writes (bijection on [0,256))
#define PHI(a) ((a) ^ (((a) >> 4) & 15))

// SMEM layout (bytes):
//   Astore : float2[16*257]  (input staging; reused as complex ping buf (stride 256)
//                             and finally as real windowed frames float[16*512])
//   Bbuf   : float2[16*256]  (complex pong buf)
//   Wt     : float2[128]     cis(+2*pi*j/256)
//   T5     : float2[256]     cis(+2*pi*k/512)
//   wshp   : float2[256]     (win[2m], win[2m+1]) / 256
//   wsq    : float [512]     win^2
#define OFF_A    0
#define OFF_B    (16 * 257 * 8)                  // 32896
#define OFF_WT   (OFF_B  + 16 * 256 * 8)         // 65664
#define OFF_T5   (OFF_WT + 128 * 8)              // 66688
#define OFF_WSHP (OFF_T5 + 256 * 8)              // 68736
#define OFF_WSQ  (OFF_WSHP + 256 * 8)            // 70784
#define SMEM_BYTES (OFF_WSQ + 512 * 4)           // 72832

__global__ __launch_bounds__(THREADS)
void istft_fused_kernel(const float2* __restrict__ X,
                        const float* __restrict__ win,
                        float* __restrict__ out)
{
    extern __shared__ char smem[];
    float2* Astore = (float2*)(smem + OFF_A);    // staging: [fr*257 + k]
    float2* A2     = (float2*)(smem + OFF_A);    // complex: [fr*256 + i]
    float*  Frf    = (float*)(smem + OFF_A);     // real frames: [fr*512 + n]
    float2* Fr2    = (float2*)(smem + OFF_A);    // same, pairwise
    float2* Bb     = (float2*)(smem + OFF_B);    // complex: [fr*256 + i]
    float2* Wt     = (float2*)(smem + OFF_WT);
    float2* T5     = (float2*)(smem + OFF_T5);
    float2* wshp   = (float2*)(smem + OFF_WSHP);
    float*  wsq    = (float*)(smem + OFF_WSQ);

    const int tid   = threadIdx.x;
    const int b     = blockIdx.x;                // chunk within stream
    const int bc    = blockIdx.y;                // which of 32 streams
    const int tbase = FADV * b - 1;              // first frame slot's t
    const int o0    = 256 + CHUNK * b;           // first absolute output sample

    // ---- tables ----
    for (int j = tid; j < 128; j += THREADS) {
        float s, c; sincospif(j * (1.0f / 128.0f), &s, &c);   // 2*pi*j/256
        Wt[j] = make_float2(c, s);
    }
    for (int k = tid; k < 256; k += THREADS) {
        float s, c; sincospif(k * (1.0f / 256.0f), &s, &c);   // 2*pi*k/512
        T5[k] = make_float2(c, s);
    }
    for (int m = tid; m < 256; m += THREADS) {
        wshp[m] = make_float2(win[2 * m] * (1.0f / 256.0f),
                              win[2 * m + 1] * (1.0f / 256.0f));
    }
    for (int n = tid; n < NFFT; n += THREADS) {
        const float w = win[n];
        wsq[n] = w * w;
    }

    // ---- stage input: 16 frames x 257 bins (t-contiguous lanes) ----
    for (int idx = tid; idx < FPB * NH; idx += THREADS) {
        const int k  = idx >> 4;
        const int fr = idx & 15;
        int t = tbase + fr;
        t = t < 0 ? 0 : (t > TFRAMES - 1 ? TFRAMES - 1 : t);  // clamp; unused slots harmless
        Astore[fr * NH + k] = X[(size_t)(bc * NH + k) * TFRAMES + t];
    }
    __syncthreads();

    // ---- pack onesided spectrum into 256-pt complex spectrum Z -> Bb (swizzled) ----
    //   Ze = (X[k] + conj(X[256-k]))/2 ; Zo = cis(2*pi*k/512) * (i/2)(X[k]-conj(X[256-k]))
    for (int idx = tid; idx < FPB * 256; idx += THREADS) {
        const int fr = idx >> 8;
        const int k  = idx & 255;
        float2 a = Astore[fr * NH + k];
        float2 t = Astore[fr * NH + (256 - k)];
        float br = t.x, bi = -t.y;
        if (k == 0) { a.y = 0.0f; bi = 0.0f; }   // C2R ignores DC/Nyquist imag
        const float zer = 0.5f * (a.x + br);
        const float zei = 0.5f * (a.y + bi);
        const float dr  = a.x - br;
        const float di  = a.y - bi;
        const float u   = -0.5f * di;
        const float v   =  0.5f * dr;
        const float2 w  = T5[k];
        Bb[fr * 256 + PHI(k)] = make_float2(zer + w.x * u - w.y * v,
                                            zei + w.x * v + w.y * u);
    }
    __syncthreads();

    // ---- 4 paired radix-2 Stockham stages (inverse, e^{+i}), unnormalized ----
    // Pair (st, st+1): inputs at i, i+64, i+128, i+192 (i = q + p<<st);
    // outputs at base + {0,1,2,3}<<st with base = q + p<<(st+2).
    {
        float2* src = Bb;
        float2* dst = A2;
        #pragma unroll
        for (int st = 0; st < 8; st += 2) {
            for (int idx = tid; idx < FPB * 64; idx += THREADS) {
                const int fr = idx >> 6;
                const int i  = idx & 63;
                const int p  = i >> st;
                const int q  = i & ((1 << st) - 1);
                const int fb = fr * 256;
                const float2 x0 = src[fb + PHI(i)];
                const float2 x1 = src[fb + PHI(i + 64)];
                const float2 x2 = src[fb + PHI(i + 128)];
                const float2 x3 = src[fb + PHI(i + 192)];
                const float2 w1 = Wt[p << st];
                // stage st
                const float2 u0 = make_float2(x0.x + x2.x, x0.y + x2.y);
                const float  d02r = x0.x - x2.x, d02i = x0.y - x2.y;
                const float2 u1 = make_float2(w1.x * d02r - w1.y * d02i,
                                              w1.x * d02i + w1.y * d02r);
                const float2 u2 = make_float2(x1.x + x3.x, x1.y + x3.y);
                const float  d13r = x1.x - x3.x, d13i = x1.y - x3.y;
                // W[p<<st + 64] = i * W[p<<st]  (inverse transform)
                const float  t3r = w1.x * d13r - w1.y * d13i;
                const float  t3i = w1.x * d13i + w1.y * d13r;
                const float2 u3 = make_float2(-t3i, t3r);
                // stage st+1 (both sub-butterflies share twiddle W[p<<(st+1)])
                const float2 w2 = Wt[p << (st + 1)];
                const float2 v0 = make_float2(u0.x + u2.x, u0.y + u2.y);
                const float  e02r = u0.x - u2.x, e02i = u0.y - u2.y;
                const float2 v1 = make_float2(w2.x * e02r - w2.y * e02i,
                                              w2.x * e02i + w2.y * e02r);
                const float2 v2 = make_float2(u1.x + u3.x, u1.y + u3.y);
                const float  e13r = u1.x - u3.x, e13i = u1.y - u3.y;
                const float2 v3 = make_float2(w2.x * e13r - w2.y * e13i,
                                              w2.x * e13i + w2.y * e13r);
                const int ob = q + (p << (st + 2));
                dst[fb + PHI(ob)]               = v0;
                dst[fb + PHI(ob + (1 << st))]   = v2;
                dst[fb + PHI(ob + (2 << st))]   = v1;
                dst[fb + PHI(ob + (3 << st))]   = v3;
            }
            __syncthreads();
            float2* tmp = src; src = dst; dst = tmp;
        }
        // 4 paired stages starting src=Bb: B->A->B->A->B, result in Bb.
    }

    // ---- unpack real output (y[2m]=Re z[m], y[2m+1]=Im z[m]) * win/256 ----
    for (int idx = tid; idx < FPB * 256; idx += THREADS) {
        const int fr = idx >> 8;
        const int m  = idx & 255;
        const float2 z = Bb[fr * 256 + PHI(m)];
        const float2 w = wshp[m];
        Fr2[fr * 256 + m] = make_float2(z.x * w.x, z.y * w.y);
    }
    __syncthreads();

    // ---- overlap-add + envelope normalize, direct to output ----
    const int nsamp = min(CHUNK, 262272 - o0);   // last chunk is partial
    for (int j = tid; j < nsamp; j += THREADS) {
        const int m = o0 + j;
        int thi = m >> 7;          if (thi > TFRAMES - 1) thi = TFRAMES - 1;
        int tlo = (m - 384) >> 7;  if (tlo < 0) tlo = 0;   // ceil((m-511)/128)
        float acc = 0.0f, env = 0.0f;
        #pragma unroll 4
        for (int t = tlo; t <= thi; t++) {
            const int n  = m - (t << 7);
            const int fr = t - tbase;            // in [0,16) by construction
            acc += Frf[fr * NFFT + n];
            env += wsq[n];
        }
        out[(size_t)bc * OUT_PER_BC + (m - 256)] = acc / env;
    }
}

extern "C" void kernel_launch(void* const* d_in, const int* in_sizes, int n_in,
                              void* d_out, int out_size)
{
    const float2* X   = (const float2*)d_in[0];   // (16,2,257,2048,2) f32
    const float*  win = (const float*)d_in[1];    // (512,) f32
    float* out = (float*)d_out;                   // (16,2,262016) f32

    cudaFuncSetAttribute(istft_fused_kernel,
                         cudaFuncAttributeMaxDynamicSharedMemorySize, SMEM_BYTES);
    dim3 grid(NCHUNK, NBC);
    istft_fused_kernel<<<grid, THREADS, SMEM_BYTES>>>(X, win, out);
}

// round 5
// speedup vs baseline: 1.4846x; 1.3984x over previous
#include <cuda_runtime.h>

// Fused ISTFT, 16x16 register-FFT version.
// B=16, C=2, F=257, T=2048, n_fft=512, hop=128, center=True.
// Block = 16 consecutive frames of one (b,c) stream; thread (fr, n1/k2) does
// 16-pt inverse FFTs in registers (256 = 16x16 decomposition); overlap-add of
// 1664 samples written directly. Single in-place SMEM buffer.

#define NFFT     512
#define NH       257
#define HOP      128
#define TFRAMES  2048
#define NBC      32
#define OUT_PER_BC 262016            // (T-1)*hop
#define THREADS  256
#define FPB      16                  // frames per block
#define FADV     13                  // frame advance per chunk
#define CHUNK    1664                // FADV*HOP
#define NCHUNK   158                 // ceil(262016/1664)
#define FRSTRIDE 265                 // float2 stride per frame row (odd)

// SMEM layout (bytes)
#define OFF_DATA 0
#define OFF_T5   (FPB * FRSTRIDE * 8)            // 33920
#define OFF_WSHP (OFF_T5 + 256 * 8)              // 35968
#define OFF_WSQ  (OFF_WSHP + 256 * 8)            // 38016
#define OFF_EINV (OFF_WSQ + 512 * 4)             // 40064
#define SMEM_BYTES (OFF_EINV + 128 * 4)          // 40576

__device__ __forceinline__ float2 cmul(float2 a, float2 b) {
    return make_float2(a.x * b.x - a.y * b.y, a.x * b.y + a.y * b.x);
}

// Fully-unrolled 16-pt inverse DFT (e^{+i}), DIF, in place.
// On exit, position j holds X[bitrev4(j)].
__device__ __forceinline__ void fft16(float2* v)
{
    const float WR[8] = { 1.f,  0.9238795325f,  0.7071067812f,  0.3826834324f,
                          0.f, -0.3826834324f, -0.7071067812f, -0.9238795325f };
    const float WI[8] = { 0.f,  0.3826834324f,  0.7071067812f,  0.9238795325f,
                          1.f,  0.9238795325f,  0.7071067812f,  0.3826834324f };
    #pragma unroll
    for (int i = 0; i < 8; i++) {                 // stage 1, stride 8, tw W16^i
        float2 a = v[i], b = v[i + 8];
        v[i] = make_float2(a.x + b.x, a.y + b.y);
        float dr = a.x - b.x, di = a.y - b.y;
        v[i + 8] = make_float2(dr * WR[i] - di * WI[i], dr * WI[i] + di * WR[i]);
    }
    #pragma unroll
    for (int bb = 0; bb < 16; bb += 8)            // stage 2, stride 4, tw W16^{2i}
        #pragma unroll
        for (int i = 0; i < 4; i++) {
            float2 a = v[bb + i], b = v[bb + i + 4];
            v[bb + i] = make_float2(a.x + b.x, a.y + b.y);
            float dr = a.x - b.x, di = a.y - b.y;
            v[bb + i + 4] = make_float2(dr * WR[2 * i] - di * WI[2 * i],
                                        dr * WI[2 * i] + di * WR[2 * i]);
        }
    #pragma unroll
    for (int bb = 0; bb < 16; bb += 4) {          // stage 3, stride 2, tw {1, i}
        float2 a = v[bb], b = v[bb + 2];
        v[bb]     = make_float2(a.x + b.x, a.y + b.y);
        v[bb + 2] = make_float2(a.x - b.x, a.y - b.y);
        a = v[bb + 1]; b = v[bb + 3];
        v[bb + 1] = make_float2(a.x + b.x, a.y + b.y);
        v[bb + 3] = make_float2(-(a.y - b.y), a.x - b.x);   // * i
    }
    #pragma unroll
    for (int bb = 0; bb < 16; bb += 2) {          // stage 4, stride 1
        float2 a = v[bb], b = v[bb + 1];
        v[bb]     = make_float2(a.x + b.x, a.y + b.y);
        v[bb + 1] = make_float2(a.x - b.x, a.y - b.y);
    }
}

__global__ __launch_bounds__(THREADS, 4)
void istft_fused16_kernel(const float2* __restrict__ X,
                          const float* __restrict__ win,
                          float* __restrict__ out)
{
    extern __shared__ char smem[];
    float2* D    = (float2*)(smem + OFF_DATA);   // [16][265] float2, in-place all phases
    float*  Frf  = (float*)(smem + OFF_DATA);    // frame floats: [fr*530 + n]
    float2* T5   = (float2*)(smem + OFF_T5);     // cis(2*pi*k/512)
    float2* wshp = (float2*)(smem + OFF_WSHP);   // (win[2m], win[2m+1]) / 256
    float*  wsq  = (float*)(smem + OFF_WSQ);     // win^2 (edge envelopes)
    float*  einv = (float*)(smem + OFF_EINV);    // 1/env for interior samples

    const int tid   = threadIdx.x;
    const int b     = blockIdx.x;
    const int bc    = blockIdx.y;
    const int tbase = FADV * b - 1;
    const int o0    = 256 + CHUNK * b;

    const int REV4[16] = {0,8,4,12,2,10,6,14,1,9,5,13,3,11,7,15};

    // ---- tables ----
    for (int k = tid; k < 256; k += THREADS) {
        float s, c; sincospif(k * (1.0f / 256.0f), &s, &c);   // 2*pi*k/512
        T5[k] = make_float2(c, s);
    }
    for (int m = tid; m < 256; m += THREADS)
        wshp[m] = make_float2(win[2 * m] * (1.0f / 256.0f),
                              win[2 * m + 1] * (1.0f / 256.0f));
    for (int n = tid; n < NFFT; n += THREADS) {
        const float w = win[n];
        wsq[n] = w * w;
    }
    if (tid < 128) {
        const float w0 = win[tid], w1 = win[tid + 128],
                    w2 = win[tid + 256], w3 = win[tid + 384];
        einv[tid] = 1.0f / (w0 * w0 + w1 * w1 + w2 * w2 + w3 * w3);
    }

    // ---- stage input: 16 frames x 257 bins ----
    for (int idx = tid; idx < FPB * NH; idx += THREADS) {
        const int k  = idx >> 4;
        const int fr = idx & 15;
        int t = tbase + fr;
        t = t < 0 ? 0 : (t > TFRAMES - 1 ? TFRAMES - 1 : t);
        D[fr * FRSTRIDE + k] = X[(size_t)(bc * NH + k) * TFRAMES + t];
    }
    __syncthreads();

    const int fr  = tid >> 4;
    const int col = tid & 15;                    // n1 for phase A, k2 for phase B
    float2* row = D + fr * FRSTRIDE;
    float2 v[16];

    // ---- phase A: pack onesided->complex on the fly, 16-pt FFT over n2 ----
    #pragma unroll
    for (int n2 = 0; n2 < 16; n2++) {
        const int n = col + 16 * n2;
        float2 a = row[n];
        float2 t = row[256 - n];
        float br = t.x, bi = -t.y;
        if (n == 0) { a.y = 0.0f; bi = 0.0f; }   // C2R ignores DC/Nyquist imag
        const float zer = 0.5f * (a.x + br);
        const float zei = 0.5f * (a.y + bi);
        const float dr  = a.x - br;
        const float di  = a.y - bi;
        const float u   = -0.5f * di;
        const float w_  =  0.5f * dr;
        const float2 w  = T5[n];
        v[n2] = make_float2(zer + w.x * u - w.y * w_,
                            zei + w.x * w_ + w.y * u);
    }
    fft16(v);
    __syncthreads();                              // all reads of D done
    {
        const float2 w = T5[2 * col];             // cis(2*pi*n1/256)
        float2 tw = make_float2(1.0f, 0.0f);
        #pragma unroll
        for (int k2 = 0; k2 < 16; k2++) {
            row[16 * k2 + (col ^ k2)] = cmul(v[REV4[k2]], tw);  // XOR-swizzled H
            tw = cmul(tw, w);
        }
    }
    __syncthreads();

    // ---- phase B: 16-pt FFT over n1, window+unpack fused into store ----
    #pragma unroll
    for (int n1 = 0; n1 < 16; n1++)
        v[n1] = row[16 * col + (n1 ^ col)];
    fft16(v);
    __syncthreads();                              // all reads of H done
    #pragma unroll
    for (int k1 = 0; k1 < 16; k1++) {
        const int m = col + 16 * k1;
        const float2 z  = v[REV4[k1]];
        const float2 wp = wshp[m];
        row[m] = make_float2(z.x * wp.x, z.y * wp.y);   // y[2m], y[2m+1] windowed
    }
    __syncthreads();

    // ---- overlap-add + envelope normalize ----
    const int nsamp = min(CHUNK, 262272 - o0);
    for (int j = tid; j < nsamp; j += THREADS) {
        const int m = o0 + j;
        int thi = m >> 7;          if (thi > TFRAMES - 1) thi = TFRAMES - 1;
        int tlo = (m - 384) >> 7;  if (tlo < 0) tlo = 0;
        float acc = 0.0f;
        #pragma unroll 4
        for (int t = tlo; t <= thi; t++)
            acc += Frf[(t - tbase) * (2 * FRSTRIDE) + (m - (t << 7))];
        float ei;
        if (m >= 384 && m < 262144) {
            ei = einv[m & 127];
        } else {
            float e = 0.0f;
            for (int t = tlo; t <= thi; t++) e += wsq[m - (t << 7)];
            ei = 1.0f / e;
        }
        out[(size_t)bc * OUT_PER_BC + (m - 256)] = acc * ei;
    }
}

extern "C" void kernel_launch(void* const* d_in, const int* in_sizes, int n_in,
                              void* d_out, int out_size)
{
    const float2* X   = (const float2*)d_in[0];   // (16,2,257,2048,2) f32
    const float*  win = (const float*)d_in[1];    // (512,) f32
    float* out = (float*)d_out;                   // (16,2,262016) f32

    dim3 grid(NCHUNK, NBC);
    istft_fused16_kernel<<<grid, THREADS, SMEM_BYTES>>>(X, win, out);
}